// round 1
// baseline (speedup 1.0000x reference)
#include <cuda_runtime.h>

#define NN 100000
#define NE 1200000
#define NTILES (NN/32)   // 3125, NN divisible by 32

// ---------------- scratch (static device memory; no runtime allocation) ----
__device__ int   g_deg[NN];
__device__ int   g_cnt[NN];
__device__ int   g_fill[NN];
__device__ int   g_rp[NN + 1];
__device__ int   g_col[NE];
__device__ float g_w[NE];
__device__ float g_dinv[NN];
__device__ float g_T1[NN * 64];
__device__ float g_T2[NN * 64];
__device__ float g_T3[NN * 64];
__device__ float g_Ha[NN * 64];
__device__ float g_Hb[NN * 64];
__device__ float g_A[NN * 32];
__device__ float g_B[NN * 32];

// ---------------- setup kernels -------------------------------------------
__global__ void k_zero3() {
    int i = blockIdx.x * blockDim.x + threadIdx.x;
    if (i < NN) { g_deg[i] = 0; g_cnt[i] = 0; g_fill[i] = 0; }
}

__global__ void k_degcnt(const int* __restrict__ src, const int* __restrict__ dst) {
    int i = blockIdx.x * blockDim.x + threadIdx.x;
    if (i < NE) {
        atomicAdd(&g_deg[src[i]], 1);
        atomicAdd(&g_cnt[dst[i]], 1);
    }
}

__global__ void k_dinv() {
    int i = blockIdx.x * blockDim.x + threadIdx.x;
    if (i < NN) {
        int d = g_deg[i];
        g_dinv[i] = (d > 0) ? rsqrtf((float)d) : 0.0f;
    }
}

// single-block exclusive scan of g_cnt -> g_rp (sequential chunks w/ carry)
__global__ void k_scan() {
    __shared__ int wsum[32];
    __shared__ int s_carry;
    const int t = threadIdx.x;  // 1024 threads
    if (t == 0) s_carry = 0;
    __syncthreads();
    for (int base = 0; base < NN; base += 1024) {
        int i = base + t;
        int v = (i < NN) ? g_cnt[i] : 0;
        int xv = v;
        #pragma unroll
        for (int d = 1; d < 32; d <<= 1) {
            int y = __shfl_up_sync(0xffffffffu, xv, d);
            if ((t & 31) >= d) xv += y;
        }
        if ((t & 31) == 31) wsum[t >> 5] = xv;
        __syncthreads();
        if (t < 32) {
            int wv = wsum[t];
            int yv = wv;
            #pragma unroll
            for (int d = 1; d < 32; d <<= 1) {
                int z = __shfl_up_sync(0xffffffffu, yv, d);
                if (t >= d) yv += z;
            }
            wsum[t] = yv - wv;  // exclusive warp offsets
        }
        __syncthreads();
        int incl = xv + wsum[t >> 5];
        int excl = incl - v + s_carry;
        if (i < NN) g_rp[i] = excl;
        __syncthreads();
        if (t == 1023) s_carry = s_carry + incl;  // chunk total
        __syncthreads();
    }
    if (t == 0) g_rp[NN] = s_carry;
}

__global__ void k_scatter(const int* __restrict__ src, const int* __restrict__ dst) {
    int i = blockIdx.x * blockDim.x + threadIdx.x;
    if (i < NE) {
        int s = src[i], d = dst[i];
        int pos = g_rp[d] + atomicAdd(&g_fill[d], 1);
        g_col[pos] = s;
        g_w[pos] = -g_dinv[s] * g_dinv[d];
    }
}

// ---------------- sparse matvec: out = alpha * (L z) + beta * sub ----------
__global__ void k_lmv64(const float* __restrict__ z, const float* __restrict__ sub,
                        float* __restrict__ outp, float alpha, float beta) {
    int gt = blockIdx.x * blockDim.x + threadIdx.x;
    int node = gt >> 5;
    if (node >= NN) return;
    int lane = gt & 31;
    int beg = g_rp[node], end = g_rp[node + 1];
    const float2* z2 = (const float2*)z;
    float2 acc = make_float2(0.f, 0.f);
    for (int e = beg; e < end; e++) {
        int s = g_col[e];
        float we = g_w[e];
        float2 v = z2[s * 32 + lane];
        acc.x += we * v.x;
        acc.y += we * v.y;
    }
    float2 r;
    if (sub) {
        float2 sv = ((const float2*)sub)[node * 32 + lane];
        r.x = alpha * acc.x + beta * sv.x;
        r.y = alpha * acc.y + beta * sv.y;
    } else {
        r.x = alpha * acc.x;
        r.y = alpha * acc.y;
    }
    ((float2*)outp)[node * 32 + lane] = r;
}

// ---------------- fused layer GEMM -----------------------------------------
// out = relu([T0|T1|T2|T3] @ Wk + bk) + T0 @ Ws + bs
// smem: Wk 16384f, Ws 4096f, ins 32x256f, bk 64f, bs 64f  -> 115200 B
#define SMEM_LAYER (28800 * 4)
__global__ void k_layer(const float* __restrict__ T0,
                        const float* __restrict__ Wk, const float* __restrict__ bk,
                        const float* __restrict__ Ws, const float* __restrict__ bs,
                        float* __restrict__ outp) {
    extern __shared__ float sm[];
    float* Wk_s = sm;            // 16384
    float* Ws_s = sm + 16384;    // 4096
    float* ins  = sm + 20480;    // 8192  [32 rows][256]
    float* bk_s = sm + 28672;    // 64
    float* bs_s = sm + 28736;    // 64
    const int t = threadIdx.x;   // 256 threads

    for (int j = t; j < 4096; j += 256) ((float4*)Wk_s)[j] = ((const float4*)Wk)[j];
    for (int j = t; j < 1024; j += 256) ((float4*)Ws_s)[j] = ((const float4*)Ws)[j];
    if (t < 64) { bk_s[t] = bk[t]; bs_s[t] = bs[t]; }

    const int cg = (t & 15) * 4;   // output col base (4 cols)
    const int r0 = (t >> 4) * 2;   // row base (2 rows)

    for (int tile = blockIdx.x; tile < NTILES; tile += gridDim.x) {
        const int rowbase = tile * 32;
        __syncthreads();
        {
            const float4* s0 = (const float4*)T0;
            const float4* s1 = (const float4*)g_T1;
            const float4* s2 = (const float4*)g_T2;
            const float4* s3 = (const float4*)g_T3;
            #pragma unroll
            for (int j = 0; j < 2; j++) {
                int i = t + j * 256;
                int r = i >> 4, f4 = i & 15;
                int gidx = (rowbase + r) * 16 + f4;
                *(float4*)&ins[r * 256 +   0 + f4 * 4] = s0[gidx];
                *(float4*)&ins[r * 256 +  64 + f4 * 4] = s1[gidx];
                *(float4*)&ins[r * 256 + 128 + f4 * 4] = s2[gidx];
                *(float4*)&ins[r * 256 + 192 + f4 * 4] = s3[gidx];
            }
        }
        __syncthreads();

        const float* in0 = &ins[r0 * 256];
        const float* in1 = in0 + 256;
        float4 acc0 = make_float4(0, 0, 0, 0), acc1 = acc0;
        #pragma unroll 8
        for (int kk = 0; kk < 256; kk++) {
            float4 wv = *(const float4*)&Wk_s[kk * 64 + cg];
            float a0 = in0[kk], a1 = in1[kk];
            acc0.x += a0 * wv.x; acc0.y += a0 * wv.y; acc0.z += a0 * wv.z; acc0.w += a0 * wv.w;
            acc1.x += a1 * wv.x; acc1.y += a1 * wv.y; acc1.z += a1 * wv.z; acc1.w += a1 * wv.w;
        }
        float4 sk0 = make_float4(0, 0, 0, 0), sk1 = sk0;
        #pragma unroll 8
        for (int kk = 0; kk < 64; kk++) {
            float4 wv = *(const float4*)&Ws_s[kk * 64 + cg];
            float a0 = in0[kk], a1 = in1[kk];
            sk0.x += a0 * wv.x; sk0.y += a0 * wv.y; sk0.z += a0 * wv.z; sk0.w += a0 * wv.w;
            sk1.x += a1 * wv.x; sk1.y += a1 * wv.y; sk1.z += a1 * wv.z; sk1.w += a1 * wv.w;
        }
        float4 bkv = *(const float4*)&bk_s[cg];
        float4 bsv = *(const float4*)&bs_s[cg];
        float4 o0, o1;
        o0.x = fmaxf(acc0.x + bkv.x, 0.f) + sk0.x + bsv.x;
        o0.y = fmaxf(acc0.y + bkv.y, 0.f) + sk0.y + bsv.y;
        o0.z = fmaxf(acc0.z + bkv.z, 0.f) + sk0.z + bsv.z;
        o0.w = fmaxf(acc0.w + bkv.w, 0.f) + sk0.w + bsv.w;
        o1.x = fmaxf(acc1.x + bkv.x, 0.f) + sk1.x + bsv.x;
        o1.y = fmaxf(acc1.y + bkv.y, 0.f) + sk1.y + bsv.y;
        o1.z = fmaxf(acc1.z + bkv.z, 0.f) + sk1.z + bsv.z;
        o1.w = fmaxf(acc1.w + bkv.w, 0.f) + sk1.w + bsv.w;
        *(float4*)&outp[(rowbase + r0) * 64 + cg]     = o0;
        *(float4*)&outp[(rowbase + r0 + 1) * 64 + cg] = o1;
    }
}

// ---------------- mix head GEMM: A = hc@W1, B = hc@W0 + b ------------------
// hc = [H | x] (128 wide). smem: Wm 8192f, ins 32x128f, mb 32f -> 49280 B
#define SMEM_MIX (12320 * 4)
__global__ void k_mixgemm(const float* __restrict__ H, const float* __restrict__ x,
                          const float* __restrict__ mw, const float* __restrict__ mb) {
    extern __shared__ float sm[];
    float* Wm_s = sm;           // 8192  [128][64]: cols 0..31 = W1, 32..63 = W0
    float* ins  = sm + 8192;    // 4096  [32 rows][128]
    float* mb_s = sm + 12288;   // 32
    const int t = threadIdx.x;

    for (int j = t; j < 8192; j += 256) {
        int f = j >> 6, col = j & 63;
        Wm_s[j] = (col < 32) ? mw[128 * 32 + f * 32 + col] : mw[f * 32 + (col - 32)];
    }
    if (t < 32) mb_s[t] = mb[t];

    const int cg = (t & 15) * 4;
    const int r0 = (t >> 4) * 2;

    for (int tile = blockIdx.x; tile < NTILES; tile += gridDim.x) {
        const int rowbase = tile * 32;
        __syncthreads();
        {
            const float4* sH = (const float4*)H;
            const float4* sx = (const float4*)x;
            #pragma unroll
            for (int j = 0; j < 2; j++) {
                int i = t + j * 256;
                int r = i >> 4, f4 = i & 15;
                int gidx = (rowbase + r) * 16 + f4;
                *(float4*)&ins[r * 128 +      f4 * 4] = sH[gidx];
                *(float4*)&ins[r * 128 + 64 + f4 * 4] = sx[gidx];
            }
        }
        __syncthreads();

        const float* in0 = &ins[r0 * 128];
        const float* in1 = in0 + 128;
        float4 acc0 = make_float4(0, 0, 0, 0), acc1 = acc0;
        #pragma unroll 8
        for (int kk = 0; kk < 128; kk++) {
            float4 wv = *(const float4*)&Wm_s[kk * 64 + cg];
            float a0 = in0[kk], a1 = in1[kk];
            acc0.x += a0 * wv.x; acc0.y += a0 * wv.y; acc0.z += a0 * wv.z; acc0.w += a0 * wv.w;
            acc1.x += a1 * wv.x; acc1.y += a1 * wv.y; acc1.z += a1 * wv.z; acc1.w += a1 * wv.w;
        }
        if (cg < 32) {
            *(float4*)&g_A[(rowbase + r0) * 32 + cg]     = acc0;
            *(float4*)&g_A[(rowbase + r0 + 1) * 32 + cg] = acc1;
        } else {
            float4 bv = *(const float4*)&mb_s[cg - 32];
            acc0.x += bv.x; acc0.y += bv.y; acc0.z += bv.z; acc0.w += bv.w;
            acc1.x += bv.x; acc1.y += bv.y; acc1.z += bv.z; acc1.w += bv.w;
            *(float4*)&g_B[(rowbase + r0) * 32 + cg - 32]     = acc0;
            *(float4*)&g_B[(rowbase + r0 + 1) * 32 + cg - 32] = acc1;
        }
    }
}

// ---------------- final: out = B + L(A) (width 32) -------------------------
__global__ void k_mixlmv(float* __restrict__ outp) {
    int gt = blockIdx.x * blockDim.x + threadIdx.x;
    int node = gt >> 5;
    if (node >= NN) return;
    int lane = gt & 31;
    int beg = g_rp[node], end = g_rp[node + 1];
    float acc = 0.f;
    for (int e = beg; e < end; e++) {
        acc += g_w[e] * g_A[g_col[e] * 32 + lane];
    }
    outp[node * 32 + lane] = g_B[node * 32 + lane] + acc;
}

// ---------------- launch ---------------------------------------------------
extern "C" void kernel_launch(void* const* d_in, const int* in_sizes, int n_in,
                              void* d_out, int out_size) {
    const float* x  = (const float*)d_in[0];
    const int*   ei = (const int*)d_in[1];
    const float* kw = (const float*)d_in[2];   // [3][4][64][64]
    const float* kb = (const float*)d_in[3];   // [3][64]
    const float* sw = (const float*)d_in[4];   // [3][64][64]
    const float* sb = (const float*)d_in[5];   // [3][64]
    const float* mw = (const float*)d_in[6];   // [2][128][32]
    const float* mb = (const float*)d_in[7];   // [32]
    float* outp = (float*)d_out;
    const int* src = ei;
    const int* dst = ei + NE;

    float *T1, *T2, *T3, *Ha, *Hb;
    cudaGetSymbolAddress((void**)&T1, g_T1);
    cudaGetSymbolAddress((void**)&T2, g_T2);
    cudaGetSymbolAddress((void**)&T3, g_T3);
    cudaGetSymbolAddress((void**)&Ha, g_Ha);
    cudaGetSymbolAddress((void**)&Hb, g_Hb);

    cudaFuncSetAttribute(k_layer, cudaFuncAttributeMaxDynamicSharedMemorySize, SMEM_LAYER);
    cudaFuncSetAttribute(k_mixgemm, cudaFuncAttributeMaxDynamicSharedMemorySize, SMEM_MIX);

    const int gE = (NE + 255) / 256;       // 4688
    const int gN = (NN + 255) / 256;       // 391
    const int gW = (NN * 32 + 255) / 256;  // 12500 (warp per node)
    const int gG = 592;                    // GEMM persistent-ish grid

    // graph setup: degrees, dinv, CSR by dst
    k_zero3<<<gN, 256>>>();
    k_degcnt<<<gE, 256>>>(src, dst);
    k_dinv<<<gN, 256>>>();
    k_scan<<<1, 1024>>>();
    k_scatter<<<gE, 256>>>(src, dst);

    // layer 0: input = x, output = Hb
    k_lmv64<<<gW, 256>>>(x, nullptr, T1, 1.f, 0.f);
    k_lmv64<<<gW, 256>>>(T1, x, T2, 2.f, -1.f);
    k_lmv64<<<gW, 256>>>(T2, T1, T3, 2.f, -1.f);
    k_layer<<<gG, 256, SMEM_LAYER>>>(x, kw, kb, sw, sb, Hb);

    // layer 1: Hb -> Ha
    k_lmv64<<<gW, 256>>>(Hb, nullptr, T1, 1.f, 0.f);
    k_lmv64<<<gW, 256>>>(T1, Hb, T2, 2.f, -1.f);
    k_lmv64<<<gW, 256>>>(T2, T1, T3, 2.f, -1.f);
    k_layer<<<gG, 256, SMEM_LAYER>>>(Hb, kw + 4 * 64 * 64, kb + 64, sw + 64 * 64, sb + 64, Ha);

    // layer 2: Ha -> Hb
    k_lmv64<<<gW, 256>>>(Ha, nullptr, T1, 1.f, 0.f);
    k_lmv64<<<gW, 256>>>(T1, Ha, T2, 2.f, -1.f);
    k_lmv64<<<gW, 256>>>(T2, T1, T3, 2.f, -1.f);
    k_layer<<<gG, 256, SMEM_LAYER>>>(Ha, kw + 8 * 64 * 64, kb + 128, sw + 2 * 64 * 64, sb + 128, Hb);

    // mix head: A = [Hb|x]@W1, B = [Hb|x]@W0 + b; out = B + L(A)
    k_mixgemm<<<gG, 256, SMEM_MIX>>>(Hb, x, mw, mb);
    k_mixlmv<<<gW, 256>>>(outp);
}